// round 8
// baseline (speedup 1.0000x reference)
#include <cuda_runtime.h>
#include <cuda_bf16.h>
#include <math.h>

// Problem constants
#define PC_SRC   64000
#define REF_SRC  80000
#define N_PC     8000
#define N_REF    10000

#define GRID     592           // 4 blocks/SM x 148 SMs, all co-resident
#define THREADS  256
#define TILE     64            // refs per smem tile
#define HTILE    32            // packed (2-ref) entries
#define PTS      1024          // points per chunk (4 per thread)

#define XC_A     8             // ceil(8000/1024)
#define YT_A     157           // ceil(10000/64)
#define XC_B     10            // ceil(10000/1024)
#define YT_B     125           // ceil(8000/64)
#define NCHUNK_A (XC_A * YT_A) // 1256
#define NCHUNK_B (XC_B * YT_B) // 1250
#define NCHUNK   (NCHUNK_A + NCHUNK_B)

#define FINF __int_as_float(0x7F800000)

// Device-global scratch (allocation forbidden)
__device__ float4   g_pcS[N_PC];    // (-2x, -2y, |c|^2, 0), centered at 0.5
__device__ float4   g_refS[N_REF];
__device__ unsigned g_min1[N_PC];   // min squared dist, uint bits (clamped >= 0)
__device__ unsigned g_min2[N_REF];
__device__ double   g_sum;
__device__ unsigned g_bar1, g_bar2, g_done, g_ticket;

typedef unsigned long long ull;

static __device__ __forceinline__ ull pack2(float lo, float hi) {
    ull r; asm("mov.b64 %0, {%1, %2};" : "=l"(r) : "f"(lo), "f"(hi)); return r;
}
static __device__ __forceinline__ void unpack2(ull v, float& lo, float& hi) {
    asm("mov.b64 {%0, %1}, %2;" : "=f"(lo), "=f"(hi) : "l"(v));
}
static __device__ __forceinline__ ull fma2(ull a, ull b, ull c) {
    ull d; asm("fma.rn.f32x2 %0, %1, %2, %3;" : "=l"(d) : "l"(a), "l"(b), "l"(c));
    return d;
}

__global__ void __launch_bounds__(THREADS, 4) chamfer_kernel(
    const float* __restrict__ pc_src, const float* __restrict__ ref_src,
    float* __restrict__ out)
{
    const int tid = threadIdx.x;
    const int bid = blockIdx.x;
    const int gtid = bid * THREADS + tid;
    const bool leader = (tid == 0);

    __shared__ float4 sXY[HTILE];   // (-2rx0,-2rx1,-2ry0,-2ry1)
    __shared__ float2 sZ[HTILE];    // (|r0|^2, |r1|^2)
    __shared__ unsigned s_w;
    __shared__ double warp_s[8];

    // ---- Phase 0: stage subsampled/centered/preprocessed points + init mins
    if (gtid < N_PC) {
        float delta = (float)(PC_SRC - 1) / (float)(N_PC - 1);  // fp32 linspace
        int idx = (int)((float)gtid * delta);                   // fp32 mul+trunc
        if (idx > PC_SRC - 1) idx = PC_SRC - 1;
        float x = pc_src[2 * idx] - 0.5f, y = pc_src[2 * idx + 1] - 0.5f;
        g_pcS[gtid] = make_float4(-2.0f * x, -2.0f * y, fmaf(x, x, y * y), 0.0f);
        g_min1[gtid] = 0x7F800000u;
    }
    if (gtid < N_REF) {
        float delta = (float)(REF_SRC - 1) / (float)(N_REF - 1);
        int idx = (int)((float)gtid * delta);
        if (idx > REF_SRC - 1) idx = REF_SRC - 1;
        float x = ref_src[2 * idx] - 0.5f, y = ref_src[2 * idx + 1] - 0.5f;
        g_refS[gtid] = make_float4(-2.0f * x, -2.0f * y, fmaf(x, x, y * y), 0.0f);
        g_min2[gtid] = 0x7F800000u;
    }
    __threadfence();
    __syncthreads();
    if (leader) {
        atomicAdd(&g_bar1, 1u);
        while (*((volatile unsigned*)&g_bar1) < GRID) __nanosleep(32);
    }
    __syncthreads();

    // ---- Phase 1: dynamic chunk loop (2506 chunks of 1024 pts x 64 refs)
    for (;;) {
        if (leader) s_w = atomicAdd(&g_ticket, 1u);
        __syncthreads();                 // all warps done with previous tile
        const unsigned w = s_w;
        if (w >= NCHUNK) break;

        int z, xc, yc;
        if (w < NCHUNK_A) { z = 0; xc = w % XC_A; yc = w / XC_A; }
        else { unsigned v = w - NCHUNK_A; z = 1; xc = v % XC_B; yc = v / XC_B; }

        const float4* __restrict__ P = z ? g_refS : g_pcS;
        const float4* __restrict__ R = z ? g_pcS  : g_refS;
        unsigned* __restrict__ gmin  = z ? g_min2 : g_min1;
        const int np = z ? N_REF : N_PC;
        const int nr = z ? N_PC  : N_REF;

        // stage packed tile (32 threads, L2-hot float4 reads)
        const int rbase = yc * TILE;
        if (tid < HTILE) {
            int r0 = rbase + 2 * tid, r1 = r0 + 1;
            float4 a = (r0 < nr) ? R[r0] : make_float4(0.f, 0.f, 1e30f, 0.f);
            float4 b = (r1 < nr) ? R[r1] : make_float4(0.f, 0.f, 1e30f, 0.f);
            sXY[tid] = make_float4(a.x, b.x, a.y, b.y);
            sZ[tid]  = make_float2(a.z, b.z);
        }
        __syncthreads();

        // 4 points per thread
        const int ib = xc * PTS + tid;
        ull px2[4], py2[4];
        float pp[4];
#pragma unroll
        for (int k = 0; k < 4; k++) {
            int i = ib + k * THREADS;
            float4 p = P[(i < np) ? i : (np - 1)];
            float x = -0.5f * p.x, y = -0.5f * p.y;
            px2[k] = pack2(x, x);
            py2[k] = pack2(y, y);
            pp[k]  = p.z;
        }

        float mA[4], mB[4];
#pragma unroll
        for (int k = 0; k < 4; k++) { mA[k] = FINF; mB[k] = FINF; }

#pragma unroll 8
        for (int j = 0; j < HTILE; j++) {
            float4 xy = sXY[j];
            float2 zz = sZ[j];
            ull rx2 = pack2(xy.x, xy.y);
            ull ry2 = pack2(xy.z, xy.w);
            ull rz2 = pack2(zz.x, zz.y);
#pragma unroll
            for (int k = 0; k < 4; k++) {
                ull t = fma2(px2[k], rx2, fma2(py2[k], ry2, rz2));
                float tl, th; unpack2(t, tl, th);
                mA[k] = fminf(mA[k], tl);
                mB[k] = fminf(mB[k], th);
            }
        }

#pragma unroll
        for (int k = 0; k < 4; k++) {
            int i = ib + k * THREADS;
            if (i < np) {
                float v = fmaxf(pp[k] + fminf(mA[k], mB[k]), 0.0f);
                atomicMin(&gmin[i], __float_as_uint(v));   // RED.MIN, no return
            }
        }
    }

    // ---- barrier 2 (all RED.MINs visible)
    __threadfence();
    __syncthreads();
    if (leader) {
        atomicAdd(&g_bar2, 1u);
        while (*((volatile unsigned*)&g_bar2) < GRID) __nanosleep(32);
    }
    __syncthreads();

    // ---- Phase 2: finish (one load + sqrt per point, 18000 pts)
    double local = 0.0;
    if (gtid < N_PC + N_REF) {
        if (gtid < N_PC)
            local = (double)sqrtf(__uint_as_float(__ldcg(&g_min1[gtid])))
                    * (0.5 / (double)N_PC);
        else
            local = (double)sqrtf(__uint_as_float(__ldcg(&g_min2[gtid - N_PC])))
                    * (0.5 / (double)N_REF);
    }
    for (int off = 16; off > 0; off >>= 1)
        local += __shfl_down_sync(0xFFFFFFFFu, local, off);
    const int wid = tid >> 5, lid = tid & 31;
    if (lid == 0) warp_s[wid] = local;
    __syncthreads();
    if (wid == 0) {
        local = (lid < 8) ? warp_s[lid] : 0.0;
        for (int off = 4; off > 0; off >>= 1)
            local += __shfl_down_sync(0xFFFFFFFFu, local, off);
        if (lid == 0) {
            if (local != 0.0) atomicAdd(&g_sum, local);
            __threadfence();
            unsigned t = atomicAdd(&g_done, 1u);
            if (t == GRID - 1) {
                // last block: publish + reset ALL state for next graph replay
                double s = *((volatile double*)&g_sum);
                out[0] = (float)s;
                g_sum = 0.0;
                g_bar1 = 0u; g_bar2 = 0u; g_ticket = 0u; g_done = 0u;
                __threadfence();
            }
        }
    }
}

extern "C" void kernel_launch(void* const* d_in, const int* in_sizes, int n_in,
                              void* d_out, int out_size)
{
    const float* pc_src  = (const float*)d_in[0];  // (1000,64,2) fp32
    const float* ref_src = (const float*)d_in[1];  // (80000,2)  fp32
    float* out = (float*)d_out;

    chamfer_kernel<<<GRID, THREADS>>>(pc_src, ref_src, out);
}

// round 10
// speedup vs baseline: 1.1404x; 1.1404x over previous
#include <cuda_runtime.h>
#include <cuda_bf16.h>
#include <math.h>

// Problem constants
#define PC_SRC   64000
#define REF_SRC  80000
#define N_PC     8000
#define N_REF    10000

#define GRID     592           // 4 blocks/SM x 148 SMs, all co-resident
#define THREADS  256
#define TILE     128           // refs per smem tile
#define HTILE    64            // packed (2-ref) entries
#define PTS      1024          // points per chunk (4 per thread)

#define XC_A     8             // ceil(8000/1024)
#define YT_A     79            // ceil(10000/128)
#define XC_B     10            // ceil(10000/1024)
#define YT_B     63            // ceil(8000/128)
#define NCHUNK_A (XC_A * YT_A) // 632
#define NCHUNK_B (XC_B * YT_B) // 630
#define NCHUNK   (NCHUNK_A + NCHUNK_B)   // 1262

#define FINF __int_as_float(0x7F800000)

// Device-global scratch (allocation forbidden)
__device__ float4   g_pcS[N_PC];    // (-2x, -2y, |c|^2, 0), centered at 0.5
__device__ float4   g_refS[N_REF];
__device__ unsigned g_min1[N_PC];   // min squared dist, uint bits (clamped >= 0)
__device__ unsigned g_min2[N_REF];
__device__ double   g_sum;
__device__ unsigned g_bar1, g_bar2, g_done;

typedef unsigned long long ull;

static __device__ __forceinline__ ull pack2(float lo, float hi) {
    ull r; asm("mov.b64 %0, {%1, %2};" : "=l"(r) : "f"(lo), "f"(hi)); return r;
}
static __device__ __forceinline__ void unpack2(ull v, float& lo, float& hi) {
    asm("mov.b64 {%0, %1}, %2;" : "=f"(lo), "=f"(hi) : "l"(v));
}
static __device__ __forceinline__ ull fma2(ull a, ull b, ull c) {
    ull d; asm("fma.rn.f32x2 %0, %1, %2, %3;" : "=l"(d) : "l"(a), "l"(b), "l"(c));
    return d;
}

__global__ void __launch_bounds__(THREADS, 4) chamfer_kernel(
    const float* __restrict__ pc_src, const float* __restrict__ ref_src,
    float* __restrict__ out)
{
    const int tid = threadIdx.x;
    const int bid = blockIdx.x;
    const int gtid = bid * THREADS + tid;
    const bool leader = (tid == 0);

    // double-buffered packed tiles -> only ONE barrier per chunk
    __shared__ float4 sXY[2][HTILE];   // (-2rx0,-2rx1,-2ry0,-2ry1)
    __shared__ float2 sZ[2][HTILE];    // (|r0|^2, |r1|^2)
    __shared__ double warp_s[8];

    // ---- Phase 0: stage subsampled/centered/preprocessed points + init mins
    if (gtid < N_PC) {
        float delta = (float)(PC_SRC - 1) / (float)(N_PC - 1);  // fp32 linspace
        int idx = (int)((float)gtid * delta);                   // fp32 mul+trunc
        if (idx > PC_SRC - 1) idx = PC_SRC - 1;
        float x = pc_src[2 * idx] - 0.5f, y = pc_src[2 * idx + 1] - 0.5f;
        g_pcS[gtid] = make_float4(-2.0f * x, -2.0f * y, fmaf(x, x, y * y), 0.0f);
        g_min1[gtid] = 0x7F800000u;
    }
    if (gtid < N_REF) {
        float delta = (float)(REF_SRC - 1) / (float)(N_REF - 1);
        int idx = (int)((float)gtid * delta);
        if (idx > REF_SRC - 1) idx = REF_SRC - 1;
        float x = ref_src[2 * idx] - 0.5f, y = ref_src[2 * idx + 1] - 0.5f;
        g_refS[gtid] = make_float4(-2.0f * x, -2.0f * y, fmaf(x, x, y * y), 0.0f);
        g_min2[gtid] = 0x7F800000u;
    }
    __threadfence();
    __syncthreads();
    if (leader) {
        atomicAdd(&g_bar1, 1u);
        while (*((volatile unsigned*)&g_bar1) < GRID) __nanosleep(32);
    }
    __syncthreads();

    // ---- Phase 1: static strided chunk loop (no atomics, no ticket chain)
    int buf = 0;
    for (unsigned w = bid; w < NCHUNK; w += GRID, buf ^= 1) {
        int z, xc, yc;
        if (w < NCHUNK_A) { z = 0; xc = (int)(w % XC_A); yc = (int)(w / XC_A); }
        else { unsigned v = w - NCHUNK_A; z = 1; xc = (int)(v % XC_B); yc = (int)(v / XC_B); }

        const float4* __restrict__ P = z ? g_refS : g_pcS;
        const float4* __restrict__ R = z ? g_pcS  : g_refS;
        unsigned* __restrict__ gmin  = z ? g_min2 : g_min1;
        const int np = z ? N_REF : N_PC;
        const int nr = z ? N_PC  : N_REF;

        // stage packed tile into buffer `buf` (64 threads; L2-hot float4 reads)
        const int rbase = yc * TILE;
        if (tid < HTILE) {
            int r0 = rbase + 2 * tid, r1 = r0 + 1;
            float4 a = (r0 < nr) ? R[r0] : make_float4(0.f, 0.f, 1e30f, 0.f);
            float4 b = (r1 < nr) ? R[r1] : make_float4(0.f, 0.f, 1e30f, 0.f);
            sXY[buf][tid] = make_float4(a.x, b.x, a.y, b.y);
            sZ[buf][tid]  = make_float2(a.z, b.z);
        }

        // 4 points per thread (independent of tile -> overlaps with stage)
        const int ib = xc * PTS + tid;
        ull px2[4], py2[4];
        float pp[4];
#pragma unroll
        for (int k = 0; k < 4; k++) {
            int i = ib + k * THREADS;
            float4 p = P[(i < np) ? i : (np - 1)];
            float x = -0.5f * p.x, y = -0.5f * p.y;
            px2[k] = pack2(x, x);
            py2[k] = pack2(y, y);
            pp[k]  = p.z;
        }

        __syncthreads();   // tile `buf` ready; prev buffer free to be restaged next iter

        float mA[4], mB[4];
#pragma unroll
        for (int k = 0; k < 4; k++) { mA[k] = FINF; mB[k] = FINF; }

#pragma unroll 4
        for (int j = 0; j < HTILE; j++) {
            float4 xy = sXY[buf][j];
            float2 zz = sZ[buf][j];
            ull rx2 = pack2(xy.x, xy.y);
            ull ry2 = pack2(xy.z, xy.w);
            ull rz2 = pack2(zz.x, zz.y);
#pragma unroll
            for (int k = 0; k < 4; k++) {
                ull t = fma2(px2[k], rx2, fma2(py2[k], ry2, rz2));
                float tl, th; unpack2(t, tl, th);
                mA[k] = fminf(mA[k], tl);
                mB[k] = fminf(mB[k], th);
            }
        }

#pragma unroll
        for (int k = 0; k < 4; k++) {
            int i = ib + k * THREADS;
            if (i < np) {
                float v = fmaxf(pp[k] + fminf(mA[k], mB[k]), 0.0f);
                atomicMin(&gmin[i], __float_as_uint(v));   // RED.MIN, no return
            }
        }
    }

    // ---- barrier 2 (all RED.MINs visible)
    __threadfence();
    __syncthreads();
    if (leader) {
        atomicAdd(&g_bar2, 1u);
        while (*((volatile unsigned*)&g_bar2) < GRID) __nanosleep(32);
    }
    __syncthreads();

    // ---- Phase 2: finish (one load + sqrt per point, 18000 pts)
    double local = 0.0;
    if (gtid < N_PC + N_REF) {
        if (gtid < N_PC)
            local = (double)sqrtf(__uint_as_float(__ldcg(&g_min1[gtid])))
                    * (0.5 / (double)N_PC);
        else
            local = (double)sqrtf(__uint_as_float(__ldcg(&g_min2[gtid - N_PC])))
                    * (0.5 / (double)N_REF);
    }
    for (int off = 16; off > 0; off >>= 1)
        local += __shfl_down_sync(0xFFFFFFFFu, local, off);
    const int wid = tid >> 5, lid = tid & 31;
    if (lid == 0) warp_s[wid] = local;
    __syncthreads();
    if (wid == 0) {
        local = (lid < 8) ? warp_s[lid] : 0.0;
        for (int off = 4; off > 0; off >>= 1)
            local += __shfl_down_sync(0xFFFFFFFFu, local, off);
        if (lid == 0) {
            if (local != 0.0) atomicAdd(&g_sum, local);
            __threadfence();
            unsigned t = atomicAdd(&g_done, 1u);
            if (t == GRID - 1) {
                // last block: publish + reset ALL state for next graph replay
                double s = *((volatile double*)&g_sum);
                out[0] = (float)s;
                g_sum = 0.0;
                g_bar1 = 0u; g_bar2 = 0u; g_done = 0u;
                __threadfence();
            }
        }
    }
}

extern "C" void kernel_launch(void* const* d_in, const int* in_sizes, int n_in,
                              void* d_out, int out_size)
{
    const float* pc_src  = (const float*)d_in[0];  // (1000,64,2) fp32
    const float* ref_src = (const float*)d_in[1];  // (80000,2)  fp32
    float* out = (float*)d_out;

    chamfer_kernel<<<GRID, THREADS>>>(pc_src, ref_src, out);
}

// round 12
// speedup vs baseline: 1.1416x; 1.0011x over previous
#include <cuda_runtime.h>
#include <cuda_bf16.h>
#include <math.h>

// Problem constants
#define PC_SRC   64000
#define REF_SRC  80000
#define N_PC     8000
#define N_REF    10000

#define GRID     592           // 4 blocks/SM x 148 SMs, all co-resident
#define THREADS  256
#define TILE     136           // refs per tile
#define HTILE    68            // packed (2-ref) entries
#define PTS      1024          // points per chunk (4 per thread)

// Direction A: P = pc (8000), R = ref (10000): 8 x-chunks * 74 y-tiles = 592
#define XC_A     8
#define YT_A     74
// Direction B: P = ref (10000), R = pc (8000): 10 x-chunks * 59 y-tiles = 590
#define XC_B     10
#define YT_B     59
#define NCHUNK_B 590

#define FINF __int_as_float(0x7F800000)

// Device-global scratch (allocation forbidden)
__device__ float4   g_pcS[N_PC];    // (-2x, -2y, |c|^2, 0), centered at 0.5
__device__ float4   g_refS[N_REF];
__device__ unsigned g_min1[N_PC];   // min squared dist, uint bits (clamped >= 0)
__device__ unsigned g_min2[N_REF];
__device__ double   g_sum;
__device__ unsigned g_bar1, g_bar2, g_done;

typedef unsigned long long ull;

static __device__ __forceinline__ ull pack2(float lo, float hi) {
    ull r; asm("mov.b64 %0, {%1, %2};" : "=l"(r) : "f"(lo), "f"(hi)); return r;
}
static __device__ __forceinline__ void unpack2(ull v, float& lo, float& hi) {
    asm("mov.b64 {%0, %1}, %2;" : "=f"(lo), "=f"(hi) : "l"(v));
}
static __device__ __forceinline__ ull fma2(ull a, ull b, ull c) {
    ull d; asm("fma.rn.f32x2 %0, %1, %2, %3;" : "=l"(d) : "l"(a), "l"(b), "l"(c));
    return d;
}

// Per-chunk compute: 4 points/thread vs one staged tile; RED.MIN result.
static __device__ __forceinline__ void run_chunk(
    const float4* __restrict__ P, unsigned* __restrict__ gmin,
    const ulonglong2* __restrict__ sXY, const ull* __restrict__ sZ,
    int np, int xc, int tid)
{
    const int ib = xc * PTS + tid;
    ull px2[4], py2[4];
    float pp[4];
#pragma unroll
    for (int k = 0; k < 4; k++) {
        int i = ib + k * THREADS;
        float4 p = P[(i < np) ? i : (np - 1)];
        float x = -0.5f * p.x, y = -0.5f * p.y;
        px2[k] = pack2(x, x);
        py2[k] = pack2(y, y);
        pp[k]  = p.z;
    }

    float mA[4], mB[4];
#pragma unroll
    for (int k = 0; k < 4; k++) { mA[k] = FINF; mB[k] = FINF; }

#pragma unroll 4
    for (int j = 0; j < HTILE; j++) {
        ulonglong2 xy = sXY[j];     // (rx2, ry2) packed
        ull rz2 = sZ[j];
#pragma unroll
        for (int k = 0; k < 4; k++) {
            ull t = fma2(px2[k], xy.x, fma2(py2[k], xy.y, rz2));
            float tl, th; unpack2(t, tl, th);
            mA[k] = fminf(mA[k], tl);
            mB[k] = fminf(mB[k], th);
        }
    }

#pragma unroll
    for (int k = 0; k < 4; k++) {
        int i = ib + k * THREADS;
        if (i < np) {
            float v = fmaxf(pp[k] + fminf(mA[k], mB[k]), 0.0f);
            atomicMin(&gmin[i], __float_as_uint(v));   // RED.MIN, no return
        }
    }
}

// Stage one packed tile (caller picks which threads execute this).
static __device__ __forceinline__ void stage_tile(
    const float4* __restrict__ R, int nr, int rbase,
    ulonglong2* __restrict__ sXY, ull* __restrict__ sZ, int lane)
{
    int r0 = rbase + 2 * lane, r1 = r0 + 1;
    float4 a = (r0 < nr) ? R[r0] : make_float4(0.f, 0.f, 1e30f, 0.f);
    float4 b = (r1 < nr) ? R[r1] : make_float4(0.f, 0.f, 1e30f, 0.f);
    sXY[lane] = make_ulonglong2(pack2(a.x, b.x), pack2(a.y, b.y));
    sZ[lane]  = pack2(a.z, b.z);
}

__global__ void __launch_bounds__(THREADS, 4) chamfer_kernel(
    const float* __restrict__ pc_src, const float* __restrict__ ref_src,
    float* __restrict__ out)
{
    const int tid = threadIdx.x;
    const int bid = blockIdx.x;
    const int gtid = bid * THREADS + tid;
    const bool leader = (tid == 0);

    __shared__ ulonglong2 sXY_A[HTILE], sXY_B[HTILE];
    __shared__ ull        sZ_A[HTILE],  sZ_B[HTILE];
    __shared__ double warp_s[8];

    // ---- Phase 0: stage subsampled/centered/preprocessed points + init mins
    if (gtid < N_PC) {
        float delta = (float)(PC_SRC - 1) / (float)(N_PC - 1);  // fp32 linspace
        int idx = (int)((float)gtid * delta);                   // fp32 mul+trunc
        if (idx > PC_SRC - 1) idx = PC_SRC - 1;
        float x = pc_src[2 * idx] - 0.5f, y = pc_src[2 * idx + 1] - 0.5f;
        g_pcS[gtid] = make_float4(-2.0f * x, -2.0f * y, fmaf(x, x, y * y), 0.0f);
        g_min1[gtid] = 0x7F800000u;
    }
    if (gtid < N_REF) {
        float delta = (float)(REF_SRC - 1) / (float)(N_REF - 1);
        int idx = (int)((float)gtid * delta);
        if (idx > REF_SRC - 1) idx = REF_SRC - 1;
        float x = ref_src[2 * idx] - 0.5f, y = ref_src[2 * idx + 1] - 0.5f;
        g_refS[gtid] = make_float4(-2.0f * x, -2.0f * y, fmaf(x, x, y * y), 0.0f);
        g_min2[gtid] = 0x7F800000u;
    }
    __threadfence();
    __syncthreads();
    if (leader) {
        atomicAdd(&g_bar1, 1u);
        while (*((volatile unsigned*)&g_bar1) < GRID) __nanosleep(32);
    }
    __syncthreads();

    // ---- Phase 1: exactly one A-chunk + one B-chunk per block (perfect balance)
    const int xcA = bid % XC_A, ycA = bid / XC_A;        // A chunk = bid (0..591)
    const bool hasB = (bid < NCHUNK_B);
    const int xcB = bid % XC_B, ycB = bid / XC_B;        // B chunk = bid (0..589)

    // stage both tiles concurrently with different warps, one barrier total
    if (tid < HTILE)
        stage_tile(g_refS, N_REF, ycA * TILE, sXY_A, sZ_A, tid);
    else if (tid >= 128 && tid < 128 + HTILE && hasB)
        stage_tile(g_pcS, N_PC, ycB * TILE, sXY_B, sZ_B, tid - 128);
    __syncthreads();

    run_chunk(g_pcS, g_min1, sXY_A, sZ_A, N_PC, xcA, tid);
    if (hasB)
        run_chunk(g_refS, g_min2, sXY_B, sZ_B, N_REF, xcB, tid);

    // ---- barrier 2 (all RED.MINs visible)
    __threadfence();
    __syncthreads();
    if (leader) {
        atomicAdd(&g_bar2, 1u);
        while (*((volatile unsigned*)&g_bar2) < GRID) __nanosleep(32);
    }
    __syncthreads();

    // ---- Phase 2: finish (one load + sqrt per point, 18000 pts)
    double local = 0.0;
    if (gtid < N_PC + N_REF) {
        if (gtid < N_PC)
            local = (double)sqrtf(__uint_as_float(__ldcg(&g_min1[gtid])))
                    * (0.5 / (double)N_PC);
        else
            local = (double)sqrtf(__uint_as_float(__ldcg(&g_min2[gtid - N_PC])))
                    * (0.5 / (double)N_REF);
    }
    for (int off = 16; off > 0; off >>= 1)
        local += __shfl_down_sync(0xFFFFFFFFu, local, off);
    const int wid = tid >> 5, lid = tid & 31;
    if (lid == 0) warp_s[wid] = local;
    __syncthreads();
    if (wid == 0) {
        local = (lid < 8) ? warp_s[lid] : 0.0;
        for (int off = 4; off > 0; off >>= 1)
            local += __shfl_down_sync(0xFFFFFFFFu, local, off);
        if (lid == 0) {
            if (local != 0.0) atomicAdd(&g_sum, local);
            __threadfence();
            unsigned t = atomicAdd(&g_done, 1u);
            if (t == GRID - 1) {
                // last block: publish + reset ALL state for next graph replay
                double s = *((volatile double*)&g_sum);
                out[0] = (float)s;
                g_sum = 0.0;
                g_bar1 = 0u; g_bar2 = 0u; g_done = 0u;
                __threadfence();
            }
        }
    }
}

extern "C" void kernel_launch(void* const* d_in, const int* in_sizes, int n_in,
                              void* d_out, int out_size)
{
    const float* pc_src  = (const float*)d_in[0];  // (1000,64,2) fp32
    const float* ref_src = (const float*)d_in[1];  // (80000,2)  fp32
    float* out = (float*)d_out;

    chamfer_kernel<<<GRID, THREADS>>>(pc_src, ref_src, out);
}